// round 12
// baseline (speedup 1.0000x reference)
#include <cuda_runtime.h>
#include <cstdint>
#include <math.h>

#define JN 24
#define EPSF 1e-8f
#define TPB 128
#define CH  23                      // staged chunks per element (joints 1..23)
#define NBLK 304                    // 2 CTAs/SM on 152 SMs
#define BUF_BYTES (TPB * CH * 16)   // 47104 per buffer
#define SMEM_BYTES (2 * BUF_BYTES)  // 94208 dynamic

// R12: cross-tile software pipelining (the R9 structure, made bubble-free).
//  - Persistent grid (304 CTAs, 2/SM), grid-stride over 4096 tiles.
//  - Double-buffered cp.async staging: tile t+1 streams while tile t
//    computes/stores -> DRAM never drains between tiles.
//  - Next tile's bl/root prefetched into registers during current compute
//    (regs are free: occupancy is smem-bound at 2 CTAs/SM).
//  - Compute/store body identical to R9 (best single-shot: 71.8us).

__device__ __forceinline__ void stg256(float* p, const float* v) {
    asm volatile(
        "st.global.v8.f32 [%0], {%1,%2,%3,%4,%5,%6,%7,%8};"
        :: "l"(p),
           "f"(v[0]), "f"(v[1]), "f"(v[2]), "f"(v[3]),
           "f"(v[4]), "f"(v[5]), "f"(v[6]), "f"(v[7])
        : "memory");
}

__device__ __forceinline__ void ldg256(const float* p, float* v) {
    asm(
        "ld.global.v8.f32 {%0,%1,%2,%3,%4,%5,%6,%7}, [%8];"
        : "=f"(v[0]), "=f"(v[1]), "=f"(v[2]), "=f"(v[3]),
          "=f"(v[4]), "=f"(v[5]), "=f"(v[6]), "=f"(v[7])
        : "l"(p));
}

__device__ __forceinline__ void cp_async16(unsigned int smem_dst, const void* gsrc) {
    asm volatile("cp.async.cg.shared.global [%0], [%1], 16;"
                 :: "r"(smem_dst), "l"(gsrc) : "memory");
}

struct Pref {                 // per-tile register-prefetched scalars
    float blv[JN];
    float4 rq;
    float p0, p1, p2;
};

__global__ __launch_bounds__(TPB) void fk_kernel(
    const float4* __restrict__ rootq,   // [B,4]  (w,x,y,z)
    const float*  __restrict__ rootp,   // [B,3]
    const float*  __restrict__ localq,  // [B,J,4] as floats
    const float*  __restrict__ bl,      // [B,J]
    const float*  __restrict__ restd,   // [J,3]
    float*        __restrict__ out,     // [B,J,3]
    int nbatch)
{
    extern __shared__ float4 sq[];      // [2][TPB*CH]
    __shared__ float sdir[JN * 3];

    const int tid = threadIdx.x;
    if (tid < JN * 3) sdir[tid] = restd[tid];

    unsigned int sq_base;
    asm("{ .reg .u64 t; cvta.to.shared.u64 t, %1; cvt.u32.u64 %0, t; }"
        : "=r"(sq_base) : "l"(sq));

    const int ntiles = (nbatch + TPB - 1) / TPB;
    int tile = blockIdx.x;
    if (tile >= ntiles) return;

    const int PAR[JN] = {-1,0,0,0,1,2,3,4,5,6,7,8,9,9,9,12,13,14,16,17,18,19,20,21};

    // ---- helpers -------------------------------------------------------
    auto stage = [&](int t, int buf) {
        const float* lqb = localq + (size_t)t * TPB * (JN * 4);
        unsigned int base = sq_base + (unsigned int)buf * BUF_BYTES;
        const int blk0 = t * TPB;
        #pragma unroll
        for (int k = 0; k < CH; k++) {
            int g = tid + k * TPB;      // 0..2943
            int e = g / CH;
            int j = 1 + (g - e * CH);   // joints 1..23
            if (blk0 + e < nbatch) {
                cp_async16(base + (unsigned int)g * 16u,
                           lqb + e * (JN * 4) + j * 4);
            }
        }
        asm volatile("cp.async.commit_group;" ::: "memory");
    };

    auto prefetch = [&](int t) -> Pref {
        Pref r;
        int b = t * TPB + tid;
        if (b < nbatch) {
            const float* blb = bl + (size_t)b * JN;
            ldg256(blb,      r.blv);
            ldg256(blb + 8,  r.blv + 8);
            ldg256(blb + 16, r.blv + 16);
            r.rq = rootq[b];
            r.p0 = rootp[3 * b + 0];
            r.p1 = rootp[3 * b + 1];
            r.p2 = rootp[3 * b + 2];
        } else {
            #pragma unroll
            for (int i = 0; i < JN; i++) r.blv[i] = 0.0f;
            r.rq = make_float4(1.f, 0.f, 0.f, 0.f);
            r.p0 = r.p1 = r.p2 = 0.0f;
        }
        return r;
    };

    // ---- pipeline ------------------------------------------------------
    stage(tile, 0);
    Pref A = prefetch(tile);
    int cur = 0;

    while (true) {
        const int nxt = tile + gridDim.x;
        const bool has_next = (nxt < ntiles);

        if (has_next) {
            stage(nxt, cur ^ 1);
            asm volatile("cp.async.wait_group 1;" ::: "memory");
        } else {
            asm volatile("cp.async.wait_group 0;" ::: "memory");
        }
        __syncthreads();

        Pref B;
        if (has_next) B = prefetch(nxt);    // LDGs overlap compute below

        // ---- compute + store tile `tile` from buffer `cur` ----
        const int b = tile * TPB + tid;
        if (b < nbatch) {
            float gqw[JN], gqx[JN], gqy[JN], gqz[JN];
            float gpx[JN], gpy[JN], gpz[JN];

            {
                float4 rq = A.rq;
                float s   = rq.x*rq.x + rq.y*rq.y + rq.z*rq.z + rq.w*rq.w;
                float inv = 1.0f / (sqrtf(s) + EPSF);
                gqw[0] = rq.x * inv; gqx[0] = rq.y * inv;
                gqy[0] = rq.z * inv; gqz[0] = rq.w * inv;
            }
            gpx[0] = A.p0; gpy[0] = A.p1; gpz[0] = A.p2;

            float sb[8];
            float* ob = out + (size_t)b * (JN * 3);

            #define EMIT(o, v)                                 \
                do {                                           \
                    sb[(o) & 7] = (v);                         \
                    if (((o) & 7) == 7)                        \
                        stg256(ob + ((o) & ~7), sb);           \
                } while (0)

            EMIT(0, gpx[0]);
            EMIT(1, gpy[0]);
            EMIT(2, gpz[0]);

            const float4* qrow = sq + (size_t)cur * (TPB * CH) + tid * CH;

            #pragma unroll
            for (int j = 1; j < JN; j++) {
                const int p = PAR[j];

                float4 c4 = qrow[j - 1];
                float s   = c4.x*c4.x + c4.y*c4.y + c4.z*c4.z + c4.w*c4.w;
                float inv = 1.0f / (sqrtf(s) + EPSF);
                float cw = c4.x * inv, cx = c4.y * inv;
                float cy = c4.z * inv, cz = c4.w * inv;

                float pw = gqw[p], px = gqx[p], py = gqy[p], pz = gqz[p];

                gqw[j] = pw*cw - px*cx - py*cy - pz*cz;
                gqx[j] = pw*cx + px*cw + py*cz - pz*cy;
                gqy[j] = pw*cy - px*cz + py*cw + pz*cx;
                gqz[j] = pw*cz + px*cy - py*cx + pz*cw;

                float dx = sdir[3*j + 0], dy = sdir[3*j + 1], dz = sdir[3*j + 2];
                float tx = 2.0f * (py*dz - pz*dy);
                float ty = 2.0f * (pz*dx - px*dz);
                float tz = 2.0f * (px*dy - py*dx);
                float rx = dx + pw*tx + (py*tz - pz*ty);
                float ry = dy + pw*ty + (pz*tx - px*tz);
                float rz = dz + pw*tz + (px*ty - py*tx);

                float L = A.blv[j];
                gpx[j] = gpx[p] + rx * L;
                gpy[j] = gpy[p] + ry * L;
                gpz[j] = gpz[p] + rz * L;

                EMIT(3*j + 0, gpx[j]);
                EMIT(3*j + 1, gpy[j]);
                EMIT(3*j + 2, gpz[j]);
            }
            #undef EMIT
        }

        if (!has_next) break;
        __syncthreads();          // all reads of buf (cur^1)'s old tile done
        A = B;
        tile = nxt;
        cur ^= 1;
    }
}

extern "C" void kernel_launch(void* const* d_in, const int* in_sizes, int n_in,
                              void* d_out, int out_size)
{
    // metadata order: root_orientation_quat [B,4], root_position [B,3],
    //                 local_joint_rotations_quat [B,J,4], bone_lengths [B,J],
    //                 rest_directions [J,3]
    const float4* rootq  = (const float4*)d_in[0];
    const float*  rootp  = (const float*)d_in[1];
    const float*  localq = (const float*)d_in[2];
    const float*  bl     = (const float*)d_in[3];
    const float*  restd  = (const float*)d_in[4];
    float*        out    = (float*)d_out;

    int nbatch = in_sizes[1] / 3;   // root_position has B*3 elements

    cudaFuncSetAttribute(fk_kernel,
                         cudaFuncAttributeMaxDynamicSharedMemorySize,
                         SMEM_BYTES);

    int ntiles = (nbatch + TPB - 1) / TPB;
    int blocks = ntiles < NBLK ? ntiles : NBLK;
    fk_kernel<<<blocks, TPB, SMEM_BYTES>>>(rootq, rootp, localq, bl, restd,
                                           out, nbatch);
}

// round 13
// speedup vs baseline: 1.1510x; 1.1510x over previous
#include <cuda_runtime.h>
#include <cstdint>
#include <math.h>

#define JN 24
#define EPSF 1e-8f
#define TPB 128

// R13 = R9 (best, 71.8us) + JOINT-split cp.async pipelining.
// Three commit groups: joints 1..8, 9..16, 17..23. Compute phase k starts
// after group k arrives while later groups still stream. Unlike the R10/R12
// failures, this keeps FULL warp width in every phase, one staging buffer
// (47.1KB -> 4 CTAs/SM), and R9's register footprint.

__device__ __forceinline__ void stg256(float* p, const float* v) {
    asm volatile(
        "st.global.v8.f32 [%0], {%1,%2,%3,%4,%5,%6,%7,%8};"
        :: "l"(p),
           "f"(v[0]), "f"(v[1]), "f"(v[2]), "f"(v[3]),
           "f"(v[4]), "f"(v[5]), "f"(v[6]), "f"(v[7])
        : "memory");
}

__device__ __forceinline__ void ldg256(const float* p, float* v) {
    asm(
        "ld.global.v8.f32 {%0,%1,%2,%3,%4,%5,%6,%7}, [%8];"
        : "=f"(v[0]), "=f"(v[1]), "=f"(v[2]), "=f"(v[3]),
          "=f"(v[4]), "=f"(v[5]), "=f"(v[6]), "=f"(v[7])
        : "l"(p));
}

__device__ __forceinline__ void cp_async16(unsigned int smem_dst, const void* gsrc) {
    asm volatile("cp.async.cg.shared.global [%0], [%1], 16;"
                 :: "r"(smem_dst), "l"(gsrc) : "memory");
}

__global__ __launch_bounds__(TPB) void fk_kernel(
    const float4* __restrict__ rootq,   // [B,4]  (w,x,y,z)
    const float*  __restrict__ rootp,   // [B,3]
    const float*  __restrict__ localq,  // [B,J,4] as floats
    const float*  __restrict__ bl,      // [B,J]
    const float*  __restrict__ restd,   // [J,3]
    float*        __restrict__ out,     // [B,J,3]
    int nbatch)
{
    __shared__ float4 sq[TPB * 23];     // quats 1..23 per element, 368B rows
    __shared__ float  sdir[JN * 3];

    const int tid = threadIdx.x;
    if (tid < JN * 3) sdir[tid] = restd[tid];

    const int blk0 = blockIdx.x * TPB;
    const int b    = blk0 + tid;
    const bool active = (b < nbatch);

    // ---- Stage local quats in 3 joint-groups (1..8 / 9..16 / 17..23) ----
    {
        unsigned int sq_base;
        asm("{ .reg .u64 t; cvta.to.shared.u64 t, %1; cvt.u32.u64 %0, t; }"
            : "=r"(sq_base) : "l"(sq));
        const float* lqb = localq + (size_t)blk0 * (JN * 4);

        // Group A: joints 1..8  (8 chunks/elem, 8 iterations)
        #pragma unroll
        for (int k = 0; k < 8; k++) {
            int g = tid + k * TPB;
            int e = g >> 3;
            int j = 1 + (g & 7);
            if (blk0 + e < nbatch)
                cp_async16(sq_base + (unsigned int)(e * 23 + (j - 1)) * 16u,
                           lqb + e * (JN * 4) + j * 4);
        }
        asm volatile("cp.async.commit_group;" ::: "memory");

        // Group B: joints 9..16
        #pragma unroll
        for (int k = 0; k < 8; k++) {
            int g = tid + k * TPB;
            int e = g >> 3;
            int j = 9 + (g & 7);
            if (blk0 + e < nbatch)
                cp_async16(sq_base + (unsigned int)(e * 23 + (j - 1)) * 16u,
                           lqb + e * (JN * 4) + j * 4);
        }
        asm volatile("cp.async.commit_group;" ::: "memory");

        // Group C: joints 17..23 (7 chunks/elem)
        #pragma unroll
        for (int k = 0; k < 7; k++) {
            int g = tid + k * TPB;
            int e = g / 7;
            int j = 17 + (g - e * 7);
            if (blk0 + e < nbatch)
                cp_async16(sq_base + (unsigned int)(e * 23 + (j - 1)) * 16u,
                           lqb + e * (JN * 4) + j * 4);
        }
        asm volatile("cp.async.commit_group;" ::: "memory");
    }

    // ---- Direct loads that overlap the async stream ----
    float blv[JN];
    float gq0w, gq0x, gq0y, gq0z, gp0x, gp0y, gp0z;
    if (active) {
        const float* blb = bl + (size_t)b * JN;
        ldg256(blb,      blv);
        ldg256(blb + 8,  blv + 8);
        ldg256(blb + 16, blv + 16);

        float4 rq = rootq[b];
        float s   = rq.x*rq.x + rq.y*rq.y + rq.z*rq.z + rq.w*rq.w;
        float inv = 1.0f / (sqrtf(s) + EPSF);
        gq0w = rq.x * inv; gq0x = rq.y * inv; gq0y = rq.z * inv; gq0z = rq.w * inv;

        gp0x = rootp[3 * b + 0];
        gp0y = rootp[3 * b + 1];
        gp0z = rootp[3 * b + 2];
    }

    const int PAR[JN] = {-1,0,0,0,1,2,3,4,5,6,7,8,9,9,9,12,13,14,16,17,18,19,20,21};

    float gqw[JN], gqx[JN], gqy[JN], gqz[JN];
    float gpx[JN], gpy[JN], gpz[JN];
    float sb[8];
    float* ob = out + (size_t)b * (JN * 3);
    const float4* qrow = sq + tid * 23;

    #define EMIT(o, v)                                 \
        do {                                           \
            sb[(o) & 7] = (v);                         \
            if (((o) & 7) == 7)                        \
                stg256(ob + ((o) & ~7), sb);           \
        } while (0)

    #define BODY(j)                                                          \
        do {                                                                 \
            const int p = PAR[j];                                            \
            float4 c4 = qrow[(j) - 1];                                       \
            float s   = c4.x*c4.x + c4.y*c4.y + c4.z*c4.z + c4.w*c4.w;       \
            float inv = 1.0f / (sqrtf(s) + EPSF);                            \
            float cw = c4.x * inv, cx = c4.y * inv;                          \
            float cy = c4.z * inv, cz = c4.w * inv;                          \
            float pw = gqw[p], px = gqx[p], py = gqy[p], pz = gqz[p];        \
            gqw[j] = pw*cw - px*cx - py*cy - pz*cz;                          \
            gqx[j] = pw*cx + px*cw + py*cz - pz*cy;                          \
            gqy[j] = pw*cy - px*cz + py*cw + pz*cx;                          \
            gqz[j] = pw*cz + px*cy - py*cx + pz*cw;                          \
            float dx = sdir[3*(j)+0], dy = sdir[3*(j)+1], dz = sdir[3*(j)+2];\
            float tx = 2.0f * (py*dz - pz*dy);                               \
            float ty = 2.0f * (pz*dx - px*dz);                               \
            float tz = 2.0f * (px*dy - py*dx);                               \
            float rx = dx + pw*tx + (py*tz - pz*ty);                         \
            float ry = dy + pw*ty + (pz*tx - px*tz);                         \
            float rz = dz + pw*tz + (px*ty - py*tx);                         \
            float L = blv[j];                                                \
            gpx[j] = gpx[p] + rx * L;                                        \
            gpy[j] = gpy[p] + ry * L;                                        \
            gpz[j] = gpz[p] + rz * L;                                        \
            EMIT(3*(j) + 0, gpx[j]);                                         \
            EMIT(3*(j) + 1, gpy[j]);                                         \
            EMIT(3*(j) + 2, gpz[j]);                                         \
        } while (0)

    // ---- Phase A: joints 1..8 (groups B, C still streaming) ----
    asm volatile("cp.async.wait_group 2;" ::: "memory");
    __syncthreads();
    if (active) {
        gqw[0] = gq0w; gqx[0] = gq0x; gqy[0] = gq0y; gqz[0] = gq0z;
        gpx[0] = gp0x; gpy[0] = gp0y; gpz[0] = gp0z;
        EMIT(0, gpx[0]);
        EMIT(1, gpy[0]);
        EMIT(2, gpz[0]);
        #pragma unroll
        for (int j = 1; j <= 8; j++) BODY(j);
    }

    // ---- Phase B: joints 9..16 (group C still streaming) ----
    asm volatile("cp.async.wait_group 1;" ::: "memory");
    __syncthreads();
    if (active) {
        #pragma unroll
        for (int j = 9; j <= 16; j++) BODY(j);
    }

    // ---- Phase C: joints 17..23 ----
    asm volatile("cp.async.wait_group 0;" ::: "memory");
    __syncthreads();
    if (active) {
        #pragma unroll
        for (int j = 17; j < JN; j++) BODY(j);
    }

    #undef BODY
    #undef EMIT
}

extern "C" void kernel_launch(void* const* d_in, const int* in_sizes, int n_in,
                              void* d_out, int out_size)
{
    // metadata order: root_orientation_quat [B,4], root_position [B,3],
    //                 local_joint_rotations_quat [B,J,4], bone_lengths [B,J],
    //                 rest_directions [J,3]
    const float4* rootq  = (const float4*)d_in[0];
    const float*  rootp  = (const float*)d_in[1];
    const float*  localq = (const float*)d_in[2];
    const float*  bl     = (const float*)d_in[3];
    const float*  restd  = (const float*)d_in[4];
    float*        out    = (float*)d_out;

    int nbatch = in_sizes[1] / 3;   // root_position has B*3 elements

    int blocks = (nbatch + TPB - 1) / TPB;
    fk_kernel<<<blocks, TPB>>>(rootq, rootp, localq, bl, restd, out, nbatch);
}